// round 11
// baseline (speedup 1.0000x reference)
#include <cuda_runtime.h>
#include <cuda_bf16.h>
#include <cstdint>

#define B_  2
#define T_  2048
#define D_  2048
#define H_  16
#define HD_ 128

// Scratch (no cudaMalloc): pre-split bf16 operands everywhere
#define QKVN ((size_t)B_ * H_ * T_ * HD_)
__device__ __nv_bfloat16 g_qh[QKVN], g_ql[QKVN];
__device__ __nv_bfloat16 g_kh[QKVN], g_kl[QKVN];
__device__ __nv_bfloat16 g_vh[QKVN], g_vl[QKVN];
__device__ __nv_bfloat16 g_xh[(size_t)B_ * T_ * D_],  g_xl[(size_t)B_ * T_ * D_];
__device__ __nv_bfloat16 g_w1h[(size_t)3 * D_ * D_],  g_w1l[(size_t)3 * D_ * D_];
__device__ __nv_bfloat16 g_w2h[(size_t)D_ * D_],      g_w2l[(size_t)D_ * D_];
__device__ __nv_bfloat16 g_ah[(size_t)B_ * T_ * D_],  g_al[(size_t)B_ * T_ * D_];

// ============================================================================
// Helpers
// ============================================================================
__device__ __forceinline__ void mma16816(float* c, const uint32_t* a, const uint32_t* b) {
    asm volatile(
        "mma.sync.aligned.m16n8k16.row.col.f32.bf16.bf16.f32 "
        "{%0,%1,%2,%3}, {%4,%5,%6,%7}, {%8,%9}, {%0,%1,%2,%3};"
        : "+f"(c[0]), "+f"(c[1]), "+f"(c[2]), "+f"(c[3])
        : "r"(a[0]), "r"(a[1]), "r"(a[2]), "r"(a[3]), "r"(b[0]), "r"(b[1]));
}
__device__ __forceinline__ uint32_t bf2_bits(__nv_bfloat162 h) {
    uint32_t u; *reinterpret_cast<__nv_bfloat162*>(&u) = h; return u;
}
__device__ __forceinline__ void split2(float x, float y, uint32_t& hi, uint32_t& lo) {
    __nv_bfloat162 h = __floats2bfloat162_rn(x, y);
    __nv_bfloat162 l = __floats2bfloat162_rn(x - __low2float(h), y - __high2float(h));
    hi = bf2_bits(h); lo = bf2_bits(l);
}
__device__ __forceinline__ void split4(float4 v, uint2& hi, uint2& lo) {
    __nv_bfloat162 h0 = __floats2bfloat162_rn(v.x, v.y);
    __nv_bfloat162 h1 = __floats2bfloat162_rn(v.z, v.w);
    __nv_bfloat162 l0 = __floats2bfloat162_rn(v.x - __low2float(h0), v.y - __high2float(h0));
    __nv_bfloat162 l1 = __floats2bfloat162_rn(v.z - __low2float(h1), v.w - __high2float(h1));
    hi = make_uint2(bf2_bits(h0), bf2_bits(h1));
    lo = make_uint2(bf2_bits(l0), bf2_bits(l1));
}
__device__ __forceinline__ uint32_t smem_u32_of(const void* p) {
    uint32_t a;
    asm("{ .reg .u64 t; cvta.to.shared.u64 t, %1; cvt.u32.u64 %0, t; }"
        : "=r"(a) : "l"(p));
    return a;
}
__device__ __forceinline__ void ldmx4t(uint32_t* r, uint32_t saddr) {
    asm volatile("ldmatrix.sync.aligned.m8n8.x4.trans.shared.b16 {%0,%1,%2,%3}, [%4];"
                 : "=r"(r[0]), "=r"(r[1]), "=r"(r[2]), "=r"(r[3]) : "r"(saddr));
}
__device__ __forceinline__ void ldmx4(uint32_t* r, uint32_t saddr) {
    asm volatile("ldmatrix.sync.aligned.m8n8.x4.shared.b16 {%0,%1,%2,%3}, [%4];"
                 : "=r"(r[0]), "=r"(r[1]), "=r"(r[2]), "=r"(r[3]) : "r"(saddr));
}
__device__ __forceinline__ void ldmx2(uint32_t* r, uint32_t saddr) {
    asm volatile("ldmatrix.sync.aligned.m8n8.x2.shared.b16 {%0,%1}, [%2];"
                 : "=r"(r[0]), "=r"(r[1]) : "r"(saddr));
}
__device__ __forceinline__ void cp16(uint32_t d, const void* s) {
    asm volatile("cp.async.cg.shared.global [%0], [%1], 16;" :: "r"(d), "l"(s) : "memory");
}
#define CP_COMMIT() asm volatile("cp.async.commit_group;" ::: "memory")
#define CP_WAIT0()  asm volatile("cp.async.wait_group 0;" ::: "memory")
#define CP_WAIT2()  asm volatile("cp.async.wait_group 2;" ::: "memory")

// ============================================================================
// fp32 -> bf16 hi/lo split kernel
// ============================================================================
__global__ __launch_bounds__(256)
void split_f32(const float* __restrict__ src, __nv_bfloat16* __restrict__ hi,
               __nv_bfloat16* __restrict__ lo, int n4)
{
    for (int i = blockIdx.x * blockDim.x + threadIdx.x; i < n4;
         i += gridDim.x * blockDim.x) {
        float4 v = reinterpret_cast<const float4*>(src)[i];
        uint2 h, l;
        split4(v, h, l);
        reinterpret_cast<uint2*>(hi)[i] = h;
        reinterpret_cast<uint2*>(lo)[i] = l;
    }
}

// ============================================================================
// All-bf16 pre-split NT GEMM, cp.async 3-stage, KC=32, pass-ordered MMAs.
// ============================================================================
#define ARP   40
#define KCH   32
#define A_ST  (256 * ARP)
#define B_ST  (128 * ARP)
#define ST_EL (2 * A_ST + 2 * B_ST)
#define G_SMEM_BYTES (3 * ST_EL * 2)

template <int MODE>
__global__ __launch_bounds__(256)
void gemm_bf16(const __nv_bfloat16* __restrict__ Ah, const __nv_bfloat16* __restrict__ Al,
               const __nv_bfloat16* __restrict__ Bh, const __nv_bfloat16* __restrict__ Bl,
               const float* __restrict__ bias, float* __restrict__ C,
               __nv_bfloat16* __restrict__ qh_o, __nv_bfloat16* __restrict__ ql_o,
               __nv_bfloat16* __restrict__ kh_o, __nv_bfloat16* __restrict__ kl_o,
               __nv_bfloat16* __restrict__ vh_o, __nv_bfloat16* __restrict__ vl_o,
               int M, int N, int K)
{
    extern __shared__ __nv_bfloat16 smem[];
    const uint32_t smb = smem_u32_of(smem);

    const int tid = threadIdx.x;
    const int wid = tid >> 5;
    const int lid = tid & 31;
    const int gid = lid >> 2;
    const int tig = lid & 3;
    const int wm  = wid >> 1;
    const int wn  = wid & 1;
    const int m0  = blockIdx.y * 256;
    const int n0  = blockIdx.x * 128;

    const __nv_bfloat16* Ahb = Ah + (size_t)m0 * K;
    const __nv_bfloat16* Alb = Al + (size_t)m0 * K;
    const __nv_bfloat16* Bhb = Bh + (size_t)n0 * K;
    const __nv_bfloat16* Blb = Bl + (size_t)n0 * K;

    float acc[4][8][4];
#pragma unroll
    for (int i = 0; i < 4; i++)
#pragma unroll
        for (int j = 0; j < 8; j++)
#pragma unroll
            for (int r = 0; r < 4; r++) acc[i][j][r] = 0.f;

    const int NC = K / KCH;

    const int lrow = tid >> 2;
    const int lc   = tid & 3;

    auto load_stage = [&](int ks, int slot) {
        const int k0 = ks * KCH;
        const uint32_t sb = smb + (uint32_t)(slot * ST_EL) * 2;
#pragma unroll
        for (int u = 0; u < 4; u++) {
            int row = lrow + u * 64;
            uint32_t d = sb + (uint32_t)(row * ARP + lc * 8) * 2;
            cp16(d, Ahb + (size_t)row * K + k0 + lc * 8);
            cp16(d + (uint32_t)A_ST * 2, Alb + (size_t)row * K + k0 + lc * 8);
        }
#pragma unroll
        for (int u = 0; u < 2; u++) {
            int row = lrow + u * 64;
            uint32_t d = sb + (uint32_t)(2 * A_ST + row * ARP + lc * 8) * 2;
            cp16(d, Bhb + (size_t)row * K + k0 + lc * 8);
            cp16(d + (uint32_t)B_ST * 2, Blb + (size_t)row * K + k0 + lc * 8);
        }
    };

#pragma unroll
    for (int s = 0; s < 3; s++) { load_stage(s, s); CP_COMMIT(); }

    const int a_lane = (lid & 15) * ARP + (lid >> 4) * 8;
    const int b_lane = (lid & 7) * ARP + ((lid >> 3) & 1) * 8;

    for (int i = 0; i < NC; i++) {
        CP_WAIT2();
        __syncthreads();

        const uint32_t sb   = smb + (uint32_t)((i % 3) * ST_EL) * 2;
        const uint32_t sbAh = sb;
        const uint32_t sbAl = sb + (uint32_t)A_ST * 2;
        const uint32_t sbBh = sb + (uint32_t)(2 * A_ST) * 2;
        const uint32_t sbBl = sb + (uint32_t)(2 * A_ST + B_ST) * 2;

#pragma unroll
        for (int kc = 0; kc < 2; kc++) {
            uint32_t ah[4][4], al[4][4];
#pragma unroll
            for (int mt = 0; mt < 4; mt++) {
                uint32_t off = (uint32_t)(((wm * 64 + mt * 16) * ARP + kc * 16 + a_lane) * 2);
                ldmx4(ah[mt], sbAh + off);
                ldmx4(al[mt], sbAl + off);
            }
#pragma unroll
            for (int ng = 0; ng < 8; ng++) {
                uint32_t off = (uint32_t)(((wn * 64 + ng * 8) * ARP + kc * 16 + b_lane) * 2);
                uint32_t bh2[2], bl2[2];
                ldmx2(bh2, sbBh + off);
                ldmx2(bl2, sbBl + off);
                // pass-ordered: 4 independent MMAs between accumulator reuse
#pragma unroll
                for (int mt = 0; mt < 4; mt++) mma16816(acc[mt][ng], ah[mt], bh2);
#pragma unroll
                for (int mt = 0; mt < 4; mt++) mma16816(acc[mt][ng], ah[mt], bl2);
#pragma unroll
                for (int mt = 0; mt < 4; mt++) mma16816(acc[mt][ng], al[mt], bh2);
            }
        }

        __syncthreads();
        if (i + 3 < NC) load_stage(i + 3, i % 3);
        CP_COMMIT();
    }

    if (MODE == 1) {
#pragma unroll
        for (int mt = 0; mt < 4; mt++) {
            int m = m0 + wm * 64 + mt * 16 + gid;
#pragma unroll
            for (int nt = 0; nt < 8; nt++) {
                int n = n0 + wn * 64 + nt * 8 + tig * 2;
                float2 v0 = make_float2(acc[mt][nt][0], acc[mt][nt][1]);
                float2 v1 = make_float2(acc[mt][nt][2], acc[mt][nt][3]);
                float b0 = bias[n], b1 = bias[n + 1];
                v0.x += b0; v0.y += b1;
                v1.x += b0; v1.y += b1;
                *(float2*)(C + (size_t)m * N + n)       = v0;
                *(float2*)(C + (size_t)(m + 8) * N + n) = v1;
            }
        }
    } else {
        const float qscale = 0.08838834764831845f;
#pragma unroll
        for (int mt = 0; mt < 4; mt++) {
            int m = m0 + wm * 64 + mt * 16 + gid;
            int bb = m >> 11, tt = m & 2047;
#pragma unroll
            for (int nt = 0; nt < 8; nt++) {
                int n = n0 + wn * 64 + nt * 8 + tig * 2;
                int tens = n >> 11;
                int dcol = n & 2047;
                int hh = dcol >> 7, hd = dcol & 127;
                size_t idx = (((size_t)(bb * 16 + hh)) * 2048 + tt) * 128 + hd;
                float sc = (tens == 0) ? qscale : 1.0f;
                uint32_t h0, l0, h1, l1;
                split2(acc[mt][nt][0] * sc, acc[mt][nt][1] * sc, h0, l0);
                split2(acc[mt][nt][2] * sc, acc[mt][nt][3] * sc, h1, l1);
                __nv_bfloat16 *dh, *dl;
                if (tens == 0)      { dh = qh_o; dl = ql_o; }
                else if (tens == 1) { dh = kh_o; dl = kl_o; }
                else                { dh = vh_o; dl = vl_o; }
                *(uint32_t*)(dh + idx) = h0;
                *(uint32_t*)(dl + idx) = l0;
                *(uint32_t*)(dh + idx + 8 * 128) = h1;
                *(uint32_t*)(dl + idx + 8 * 128) = l1;
            }
        }
    }
}

// ============================================================================
// HMMA causal flash attention — pass-ordered MMAs (groups of 4 accumulators)
// ============================================================================
#define AST 152
#define STG (64 * AST)
#define FL_STAGE (4 * STG)
#define FL_SMEM_BYTES (2 * FL_STAGE * 2)

__global__ __launch_bounds__(256)
void flash_hmma2(const __nv_bfloat16* __restrict__ QH, const __nv_bfloat16* __restrict__ QL,
                 const __nv_bfloat16* __restrict__ KHg, const __nv_bfloat16* __restrict__ KLg,
                 const __nv_bfloat16* __restrict__ VHg, const __nv_bfloat16* __restrict__ VLg,
                 __nv_bfloat16* __restrict__ OH, __nv_bfloat16* __restrict__ OL)
{
    extern __shared__ __nv_bfloat16 asm_[];
    const uint32_t smb = smem_u32_of(asm_);

    const int qb  = blockIdx.x;
    const int bh  = blockIdx.y;
    const int b   = bh >> 4;
    const int h   = bh & 15;
    const int tid = threadIdx.x;
    const int wid = tid >> 5;
    const int lid = tid & 31;
    const int gid = lid >> 2;
    const int tig = lid & 3;

    const size_t hb = (size_t)bh * T_ * HD_;

    const int r0 = qb * 128 + wid * 16 + gid;
    uint32_t qh[8][4], ql[8][4];
    {
        const __nv_bfloat16* q0h = QH + hb + (size_t)r0 * HD_;
        const __nv_bfloat16* q1h = QH + hb + (size_t)(r0 + 8) * HD_;
        const __nv_bfloat16* q0l = QL + hb + (size_t)r0 * HD_;
        const __nv_bfloat16* q1l = QL + hb + (size_t)(r0 + 8) * HD_;
#pragma unroll
        for (int kc = 0; kc < 8; kc++) {
            int c = kc * 16 + 2 * tig;
            qh[kc][0] = *(const uint32_t*)(q0h + c);
            qh[kc][1] = *(const uint32_t*)(q1h + c);
            qh[kc][2] = *(const uint32_t*)(q0h + c + 8);
            qh[kc][3] = *(const uint32_t*)(q1h + c + 8);
            ql[kc][0] = *(const uint32_t*)(q0l + c);
            ql[kc][1] = *(const uint32_t*)(q1l + c);
            ql[kc][2] = *(const uint32_t*)(q0l + c + 8);
            ql[kc][3] = *(const uint32_t*)(q1l + c + 8);
        }
    }

    float m0 = -1e30f, m1 = -1e30f, l0 = 0.f, l1 = 0.f;
    float o[16][4];
#pragma unroll
    for (int i = 0; i < 16; i++)
#pragma unroll
        for (int r = 0; r < 4; r++) o[i][r] = 0.f;

    const int lu = tid & 63;
    const int la = tid >> 6;
    const __nv_bfloat16* lg =
        (la == 0) ? (KHg + hb) : (la == 1) ? (KLg + hb)
      : (la == 2) ? (VHg + hb) : (VLg + hb);

    const uint32_t lmoff = (uint32_t)(((lid & 7) * AST + (lid >> 3) * 8) * 2);
    const uint32_t voff  = (uint32_t)(((lid & 15) * AST + (lid >> 4) * 8) * 2);

    const int ntiles = 2 * qb + 2;

    {
        uint32_t sd = smb + (uint32_t)(la * STG) * 2;
#pragma unroll
        for (int i = 0; i < 16; i++) {
            int cid = lu + 64 * i;
            int row = cid >> 4, col = cid & 15;
            cp16(sd + (uint32_t)(row * AST + col * 8) * 2,
                 lg + (size_t)row * HD_ + col * 8);
        }
    }
    CP_COMMIT();

    for (int kb = 0; kb < ntiles; kb++) {
        CP_WAIT0();
        __syncthreads();

        if (kb + 1 < ntiles) {
            uint32_t sd = smb + (uint32_t)(((kb + 1) & 1) * FL_STAGE + la * STG) * 2;
            const __nv_bfloat16* gs = lg + (size_t)((kb + 1) * 64) * HD_;
#pragma unroll
            for (int i = 0; i < 16; i++) {
                int cid = lu + 64 * i;
                int row = cid >> 4, col = cid & 15;
                cp16(sd + (uint32_t)(row * AST + col * 8) * 2,
                     gs + (size_t)row * HD_ + col * 8);
            }
            CP_COMMIT();
        }

        if (kb * 64 > qb * 128 + wid * 16 + 15) continue;

        const int st = kb & 1;
        const uint32_t kh_s = smb + (uint32_t)(st * FL_STAGE) * 2;
        const uint32_t kl_s = kh_s + (uint32_t)STG * 2;
        const uint32_t vh_s = kh_s + (uint32_t)(2 * STG) * 2;
        const uint32_t vl_s = kh_s + (uint32_t)(3 * STG) * 2;

        // ---- S = Q K^T : groups of 4 nt, pass-ordered (4 indep MMAs/pass)
        float s[8][4];
#pragma unroll
        for (int nt = 0; nt < 8; nt++)
#pragma unroll
            for (int r = 0; r < 4; r++) s[nt][r] = 0.f;

#pragma unroll
        for (int kcp = 0; kcp < 4; kcp++) {
#pragma unroll
            for (int g = 0; g < 2; g++) {
                uint32_t bf[4][4];
#pragma unroll
                for (int j = 0; j < 4; j++)
                    ldmx4(bf[j], kh_s + (uint32_t)((g * 4 + j) * 8 * AST * 2 + kcp * 64) + lmoff);
#pragma unroll
                for (int j = 0; j < 4; j++) mma16816(s[g * 4 + j], qh[2 * kcp],     bf[j]);
#pragma unroll
                for (int j = 0; j < 4; j++) mma16816(s[g * 4 + j], qh[2 * kcp + 1], bf[j] + 2);
#pragma unroll
                for (int j = 0; j < 4; j++) mma16816(s[g * 4 + j], ql[2 * kcp],     bf[j]);
#pragma unroll
                for (int j = 0; j < 4; j++) mma16816(s[g * 4 + j], ql[2 * kcp + 1], bf[j] + 2);
#pragma unroll
                for (int j = 0; j < 4; j++)
                    ldmx4(bf[j], kl_s + (uint32_t)((g * 4 + j) * 8 * AST * 2 + kcp * 64) + lmoff);
#pragma unroll
                for (int j = 0; j < 4; j++) mma16816(s[g * 4 + j], qh[2 * kcp],     bf[j]);
#pragma unroll
                for (int j = 0; j < 4; j++) mma16816(s[g * 4 + j], qh[2 * kcp + 1], bf[j] + 2);
            }
        }

        if (kb * 64 + 63 > qb * 128 + wid * 16) {
            const int rr0 = r0, rr1 = r0 + 8;
#pragma unroll
            for (int nt = 0; nt < 8; nt++) {
                int c0 = kb * 64 + nt * 8 + 2 * tig;
                int c1 = c0 + 1;
                if (c0 > rr0) s[nt][0] = -1e30f;
                if (c1 > rr0) s[nt][1] = -1e30f;
                if (c0 > rr1) s[nt][2] = -1e30f;
                if (c1 > rr1) s[nt][3] = -1e30f;
            }
        }

        float mx0 = -1e30f, mx1 = -1e30f;
#pragma unroll
        for (int nt = 0; nt < 8; nt++) {
            mx0 = fmaxf(mx0, fmaxf(s[nt][0], s[nt][1]));
            mx1 = fmaxf(mx1, fmaxf(s[nt][2], s[nt][3]));
        }
        mx0 = fmaxf(mx0, __shfl_xor_sync(0xFFFFFFFF, mx0, 1));
        mx0 = fmaxf(mx0, __shfl_xor_sync(0xFFFFFFFF, mx0, 2));
        mx1 = fmaxf(mx1, __shfl_xor_sync(0xFFFFFFFF, mx1, 1));
        mx1 = fmaxf(mx1, __shfl_xor_sync(0xFFFFFFFF, mx1, 2));
        float mn0 = fmaxf(m0, mx0), mn1 = fmaxf(m1, mx1);
        float a0 = __expf(m0 - mn0), a1 = __expf(m1 - mn1);
        m0 = mn0; m1 = mn1;

        float ps0 = 0.f, ps1 = 0.f;
#pragma unroll
        for (int nt = 0; nt < 8; nt++) {
            s[nt][0] = __expf(s[nt][0] - mn0); ps0 += s[nt][0];
            s[nt][1] = __expf(s[nt][1] - mn0); ps0 += s[nt][1];
            s[nt][2] = __expf(s[nt][2] - mn1); ps1 += s[nt][2];
            s[nt][3] = __expf(s[nt][3] - mn1); ps1 += s[nt][3];
        }
        ps0 += __shfl_xor_sync(0xFFFFFFFF, ps0, 1);
        ps0 += __shfl_xor_sync(0xFFFFFFFF, ps0, 2);
        ps1 += __shfl_xor_sync(0xFFFFFFFF, ps1, 1);
        ps1 += __shfl_xor_sync(0xFFFFFFFF, ps1, 2);
        l0 = l0 * a0 + ps0;
        l1 = l1 * a1 + ps1;

#pragma unroll
        for (int nt = 0; nt < 16; nt++) {
            o[nt][0] *= a0; o[nt][1] *= a0;
            o[nt][2] *= a1; o[nt][3] *= a1;
        }

        // ---- O += P V : groups of 4 ntp, pass-ordered
#pragma unroll
        for (int kt = 0; kt < 4; kt++) {
            uint32_t aph[4], apl[4];
            split2(s[2 * kt][0],     s[2 * kt][1],     aph[0], apl[0]);
            split2(s[2 * kt][2],     s[2 * kt][3],     aph[1], apl[1]);
            split2(s[2 * kt + 1][0], s[2 * kt + 1][1], aph[2], apl[2]);
            split2(s[2 * kt + 1][2], s[2 * kt + 1][3], aph[3], apl[3]);
            const uint32_t ktoff = (uint32_t)(kt * 16 * AST * 2);
#pragma unroll
            for (int g = 0; g < 2; g++) {
                uint32_t vf[4][4];
#pragma unroll
                for (int j = 0; j < 4; j++)
                    ldmx4t(vf[j], vh_s + ktoff + (uint32_t)((g * 4 + j) * 32) + voff);
#pragma unroll
                for (int j = 0; j < 4; j++) mma16816(o[2 * (g * 4 + j)],     aph, vf[j]);
#pragma unroll
                for (int j = 0; j < 4; j++) mma16816(o[2 * (g * 4 + j) + 1], aph, vf[j] + 2);
#pragma unroll
                for (int j = 0; j < 4; j++) mma16816(o[2 * (g * 4 + j)],     apl, vf[j]);
#pragma unroll
                for (int j = 0; j < 4; j++) mma16816(o[2 * (g * 4 + j) + 1], apl, vf[j] + 2);
#pragma unroll
                for (int j = 0; j < 4; j++)
                    ldmx4t(vf[j], vl_s + ktoff + (uint32_t)((g * 4 + j) * 32) + voff);
#pragma unroll
                for (int j = 0; j < 4; j++) mma16816(o[2 * (g * 4 + j)],     aph, vf[j]);
#pragma unroll
                for (int j = 0; j < 4; j++) mma16816(o[2 * (g * 4 + j) + 1], aph, vf[j] + 2);
            }
        }
    }

    // ---- normalize + write pre-split bf16 [B,T,D]
    float il0 = 1.f / l0, il1 = 1.f / l1;
    size_t base0 = ((size_t)b * T_ + r0) * D_ + h * HD_;
    size_t base1 = ((size_t)b * T_ + r0 + 8) * D_ + h * HD_;
#pragma unroll
    for (int nt = 0; nt < 16; nt++) {
        uint32_t h0, lo0, h1, lo1;
        split2(o[nt][0] * il0, o[nt][1] * il0, h0, lo0);
        split2(o[nt][2] * il1, o[nt][3] * il1, h1, lo1);
        size_t c = nt * 8 + 2 * tig;
        *(uint32_t*)(OH + base0 + c) = h0;
        *(uint32_t*)(OL + base0 + c) = lo0;
        *(uint32_t*)(OH + base1 + c) = h1;
        *(uint32_t*)(OL + base1 + c) = lo1;
    }
}

// ---------------------------------------------------------------------------
extern "C" void kernel_launch(void* const* d_in, const int* in_sizes, int n_in,
                              void* d_out, int out_size)
{
    (void)in_sizes; (void)n_in; (void)out_size;
    const float* x    = (const float*)d_in[0];
    const float* wqkv = (const float*)d_in[2];
    const float* wout = (const float*)d_in[3];
    const float* bout = (const float*)d_in[4];
    float* outp = (float*)d_out;

    __nv_bfloat16 *qh_p, *ql_p, *kh_p, *kl_p, *vh_p, *vl_p;
    __nv_bfloat16 *xh_p, *xl_p, *w1h_p, *w1l_p, *w2h_p, *w2l_p, *ah_p, *al_p;
    cudaGetSymbolAddress((void**)&qh_p, g_qh);
    cudaGetSymbolAddress((void**)&ql_p, g_ql);
    cudaGetSymbolAddress((void**)&kh_p, g_kh);
    cudaGetSymbolAddress((void**)&kl_p, g_kl);
    cudaGetSymbolAddress((void**)&vh_p, g_vh);
    cudaGetSymbolAddress((void**)&vl_p, g_vl);
    cudaGetSymbolAddress((void**)&xh_p, g_xh);
    cudaGetSymbolAddress((void**)&xl_p, g_xl);
    cudaGetSymbolAddress((void**)&w1h_p, g_w1h);
    cudaGetSymbolAddress((void**)&w1l_p, g_w1l);
    cudaGetSymbolAddress((void**)&w2h_p, g_w2h);
    cudaGetSymbolAddress((void**)&w2l_p, g_w2l);
    cudaGetSymbolAddress((void**)&ah_p, g_ah);
    cudaGetSymbolAddress((void**)&al_p, g_al);

    cudaFuncSetAttribute(gemm_bf16<1>,
                         cudaFuncAttributeMaxDynamicSharedMemorySize, G_SMEM_BYTES);
    cudaFuncSetAttribute(gemm_bf16<2>,
                         cudaFuncAttributeMaxDynamicSharedMemorySize, G_SMEM_BYTES);
    cudaFuncSetAttribute(flash_hmma2,
                         cudaFuncAttributeMaxDynamicSharedMemorySize, FL_SMEM_BYTES);

    // 0) split inputs into bf16 hi/lo
    split_f32<<<592, 256>>>(x,    xh_p,  xl_p,  (B_ * T_ * D_) / 4);
    split_f32<<<592, 256>>>(wqkv, w1h_p, w1l_p, (3 * D_ * D_) / 4);
    split_f32<<<592, 256>>>(wout, w2h_p, w2l_p, (D_ * D_) / 4);

    // 1) QKV projection + fused split/scale epilogue
    dim3 g1((3 * D_) / 128, (B_ * T_) / 256);
    gemm_bf16<2><<<g1, 256, G_SMEM_BYTES>>>(xh_p, xl_p, w1h_p, w1l_p,
                                            nullptr, nullptr,
                                            qh_p, ql_p, kh_p, kl_p, vh_p, vl_p,
                                            B_ * T_, 3 * D_, D_);

    // 2) causal flash attention -> pre-split bf16 output
    dim3 g2(T_ / 128, B_ * H_);
    flash_hmma2<<<g2, 256, FL_SMEM_BYTES>>>(qh_p, ql_p, kh_p, kl_p, vh_p, vl_p,
                                            ah_p, al_p);

    // 3) output projection + bias
    dim3 g3(D_ / 128, (B_ * T_) / 256);
    gemm_bf16<1><<<g3, 256, G_SMEM_BYTES>>>(ah_p, al_p, w2h_p, w2l_p,
                                            bout, outp,
                                            nullptr, nullptr, nullptr, nullptr,
                                            nullptr, nullptr,
                                            B_ * T_, D_, D_);
}

// round 13
// speedup vs baseline: 1.5124x; 1.5124x over previous
#include <cuda_runtime.h>
#include <cuda_bf16.h>
#include <cstdint>

#define B_  2
#define T_  2048
#define D_  2048
#define H_  16
#define HD_ 128

// Scratch (no cudaMalloc): pre-split bf16 operands everywhere
#define QKVN ((size_t)B_ * H_ * T_ * HD_)
__device__ __nv_bfloat16 g_qh[QKVN], g_ql[QKVN];
__device__ __nv_bfloat16 g_kh[QKVN], g_kl[QKVN];
__device__ __nv_bfloat16 g_vh[QKVN], g_vl[QKVN];
__device__ __nv_bfloat16 g_xh[(size_t)B_ * T_ * D_],  g_xl[(size_t)B_ * T_ * D_];
__device__ __nv_bfloat16 g_w1h[(size_t)3 * D_ * D_],  g_w1l[(size_t)3 * D_ * D_];
__device__ __nv_bfloat16 g_w2h[(size_t)D_ * D_],      g_w2l[(size_t)D_ * D_];
__device__ __nv_bfloat16 g_ah[(size_t)B_ * T_ * D_],  g_al[(size_t)B_ * T_ * D_];

// ============================================================================
// Helpers
// ============================================================================
__device__ __forceinline__ void mma16816(float* c, const uint32_t* a, const uint32_t* b) {
    asm volatile(
        "mma.sync.aligned.m16n8k16.row.col.f32.bf16.bf16.f32 "
        "{%0,%1,%2,%3}, {%4,%5,%6,%7}, {%8,%9}, {%0,%1,%2,%3};"
        : "+f"(c[0]), "+f"(c[1]), "+f"(c[2]), "+f"(c[3])
        : "r"(a[0]), "r"(a[1]), "r"(a[2]), "r"(a[3]), "r"(b[0]), "r"(b[1]));
}
__device__ __forceinline__ uint32_t bf2_bits(__nv_bfloat162 h) {
    uint32_t u; *reinterpret_cast<__nv_bfloat162*>(&u) = h; return u;
}
__device__ __forceinline__ void split2(float x, float y, uint32_t& hi, uint32_t& lo) {
    __nv_bfloat162 h = __floats2bfloat162_rn(x, y);
    __nv_bfloat162 l = __floats2bfloat162_rn(x - __low2float(h), y - __high2float(h));
    hi = bf2_bits(h); lo = bf2_bits(l);
}
__device__ __forceinline__ void split4(float4 v, uint2& hi, uint2& lo) {
    __nv_bfloat162 h0 = __floats2bfloat162_rn(v.x, v.y);
    __nv_bfloat162 h1 = __floats2bfloat162_rn(v.z, v.w);
    __nv_bfloat162 l0 = __floats2bfloat162_rn(v.x - __low2float(h0), v.y - __high2float(h0));
    __nv_bfloat162 l1 = __floats2bfloat162_rn(v.z - __low2float(h1), v.w - __high2float(h1));
    hi = make_uint2(bf2_bits(h0), bf2_bits(h1));
    lo = make_uint2(bf2_bits(l0), bf2_bits(l1));
}
__device__ __forceinline__ uint32_t smem_u32_of(const void* p) {
    uint32_t a;
    asm("{ .reg .u64 t; cvta.to.shared.u64 t, %1; cvt.u32.u64 %0, t; }"
        : "=r"(a) : "l"(p));
    return a;
}
__device__ __forceinline__ void ldmx4t(uint32_t* r, uint32_t saddr) {
    asm volatile("ldmatrix.sync.aligned.m8n8.x4.trans.shared.b16 {%0,%1,%2,%3}, [%4];"
                 : "=r"(r[0]), "=r"(r[1]), "=r"(r[2]), "=r"(r[3]) : "r"(saddr));
}
__device__ __forceinline__ void ldmx4(uint32_t* r, uint32_t saddr) {
    asm volatile("ldmatrix.sync.aligned.m8n8.x4.shared.b16 {%0,%1,%2,%3}, [%4];"
                 : "=r"(r[0]), "=r"(r[1]), "=r"(r[2]), "=r"(r[3]) : "r"(saddr));
}
__device__ __forceinline__ void ldmx2(uint32_t* r, uint32_t saddr) {
    asm volatile("ldmatrix.sync.aligned.m8n8.x2.shared.b16 {%0,%1}, [%2];"
                 : "=r"(r[0]), "=r"(r[1]) : "r"(saddr));
}
__device__ __forceinline__ void cp16(uint32_t d, const void* s) {
    asm volatile("cp.async.cg.shared.global [%0], [%1], 16;" :: "r"(d), "l"(s) : "memory");
}
#define CP_COMMIT() asm volatile("cp.async.commit_group;" ::: "memory")
#define CP_WAIT0()  asm volatile("cp.async.wait_group 0;" ::: "memory")
#define CP_WAIT2()  asm volatile("cp.async.wait_group 2;" ::: "memory")

// ============================================================================
// fp32 -> bf16 hi/lo split kernel
// ============================================================================
__global__ __launch_bounds__(256)
void split_f32(const float* __restrict__ src, __nv_bfloat16* __restrict__ hi,
               __nv_bfloat16* __restrict__ lo, int n4)
{
    for (int i = blockIdx.x * blockDim.x + threadIdx.x; i < n4;
         i += gridDim.x * blockDim.x) {
        float4 v = reinterpret_cast<const float4*>(src)[i];
        uint2 h, l;
        split4(v, h, l);
        reinterpret_cast<uint2*>(hi)[i] = h;
        reinterpret_cast<uint2*>(lo)[i] = l;
    }
}

// ============================================================================
// All-bf16 pre-split NT GEMM, cp.async 3-stage, KC=32.
// NOW: 512 threads / 16 warps (warp grid 8m x 2n, warp tile 32x64) ->
// 4 warps/SMSP for latency hiding. acc=64 regs/thread, fits 128-reg cap.
// ============================================================================
#define ARP   40
#define KCH   32
#define A_ST  (256 * ARP)
#define B_ST  (128 * ARP)
#define ST_EL (2 * A_ST + 2 * B_ST)
#define G_SMEM_BYTES (3 * ST_EL * 2)

template <int MODE>
__global__ __launch_bounds__(512)
void gemm_bf16(const __nv_bfloat16* __restrict__ Ah, const __nv_bfloat16* __restrict__ Al,
               const __nv_bfloat16* __restrict__ Bh, const __nv_bfloat16* __restrict__ Bl,
               const float* __restrict__ bias, float* __restrict__ C,
               __nv_bfloat16* __restrict__ qh_o, __nv_bfloat16* __restrict__ ql_o,
               __nv_bfloat16* __restrict__ kh_o, __nv_bfloat16* __restrict__ kl_o,
               __nv_bfloat16* __restrict__ vh_o, __nv_bfloat16* __restrict__ vl_o,
               int M, int N, int K)
{
    extern __shared__ __nv_bfloat16 smem[];
    const uint32_t smb = smem_u32_of(smem);

    const int tid = threadIdx.x;
    const int wid = tid >> 5;          // 0..15
    const int lid = tid & 31;
    const int gid = lid >> 2;
    const int tig = lid & 3;
    const int wm  = wid >> 1;          // 0..7 (32-row slabs)
    const int wn  = wid & 1;           // 0..1 (64-col slabs)
    const int m0  = blockIdx.y * 256;
    const int n0  = blockIdx.x * 128;

    const __nv_bfloat16* Ahb = Ah + (size_t)m0 * K;
    const __nv_bfloat16* Alb = Al + (size_t)m0 * K;
    const __nv_bfloat16* Bhb = Bh + (size_t)n0 * K;
    const __nv_bfloat16* Blb = Bl + (size_t)n0 * K;

    float acc[2][8][4];
#pragma unroll
    for (int i = 0; i < 2; i++)
#pragma unroll
        for (int j = 0; j < 8; j++)
#pragma unroll
            for (int r = 0; r < 4; r++) acc[i][j][r] = 0.f;

    const int NC = K / KCH;

    // loader: 512 threads, 6 cp16 each per stage
    const int lrow = tid >> 2;          // 0..127
    const int lc   = tid & 3;

    auto load_stage = [&](int ks, int slot) {
        const int k0 = ks * KCH;
        const uint32_t sb = smb + (uint32_t)(slot * ST_EL) * 2;
#pragma unroll
        for (int u = 0; u < 2; u++) {
            int row = lrow + u * 128;
            uint32_t d = sb + (uint32_t)(row * ARP + lc * 8) * 2;
            cp16(d, Ahb + (size_t)row * K + k0 + lc * 8);
            cp16(d + (uint32_t)A_ST * 2, Alb + (size_t)row * K + k0 + lc * 8);
        }
        {
            int row = lrow;             // 0..127
            uint32_t d = sb + (uint32_t)(2 * A_ST + row * ARP + lc * 8) * 2;
            cp16(d, Bhb + (size_t)row * K + k0 + lc * 8);
            cp16(d + (uint32_t)B_ST * 2, Blb + (size_t)row * K + k0 + lc * 8);
        }
    };

#pragma unroll
    for (int s = 0; s < 3; s++) { load_stage(s, s); CP_COMMIT(); }

    const int a_lane = (lid & 15) * ARP + (lid >> 4) * 8;
    const int b_lane = (lid & 7) * ARP + ((lid >> 3) & 1) * 8;

    for (int i = 0; i < NC; i++) {
        CP_WAIT2();
        __syncthreads();

        const uint32_t sb   = smb + (uint32_t)((i % 3) * ST_EL) * 2;
        const uint32_t sbAh = sb;
        const uint32_t sbAl = sb + (uint32_t)A_ST * 2;
        const uint32_t sbBh = sb + (uint32_t)(2 * A_ST) * 2;
        const uint32_t sbBl = sb + (uint32_t)(2 * A_ST + B_ST) * 2;

#pragma unroll
        for (int kc = 0; kc < 2; kc++) {
            uint32_t ah[2][4], al[2][4];
#pragma unroll
            for (int mt = 0; mt < 2; mt++) {
                uint32_t off = (uint32_t)(((wm * 32 + mt * 16) * ARP + kc * 16 + a_lane) * 2);
                ldmx4(ah[mt], sbAh + off);
                ldmx4(al[mt], sbAl + off);
            }
#pragma unroll
            for (int ng = 0; ng < 8; ng++) {
                uint32_t off = (uint32_t)(((wn * 64 + ng * 8) * ARP + kc * 16 + b_lane) * 2);
                uint32_t bh2[2], bl2[2];
                ldmx2(bh2, sbBh + off);
                ldmx2(bl2, sbBl + off);
#pragma unroll
                for (int mt = 0; mt < 2; mt++) {
                    mma16816(acc[mt][ng], ah[mt], bh2);
                    mma16816(acc[mt][ng], ah[mt], bl2);
                    mma16816(acc[mt][ng], al[mt], bh2);
                }
            }
        }

        __syncthreads();
        if (i + 3 < NC) load_stage(i + 3, i % 3);
        CP_COMMIT();
    }

    if (MODE == 1) {
#pragma unroll
        for (int mt = 0; mt < 2; mt++) {
            int m = m0 + wm * 32 + mt * 16 + gid;
#pragma unroll
            for (int nt = 0; nt < 8; nt++) {
                int n = n0 + wn * 64 + nt * 8 + tig * 2;
                float2 v0 = make_float2(acc[mt][nt][0], acc[mt][nt][1]);
                float2 v1 = make_float2(acc[mt][nt][2], acc[mt][nt][3]);
                float b0 = bias[n], b1 = bias[n + 1];
                v0.x += b0; v0.y += b1;
                v1.x += b0; v1.y += b1;
                *(float2*)(C + (size_t)m * N + n)       = v0;
                *(float2*)(C + (size_t)(m + 8) * N + n) = v1;
            }
        }
    } else {
        const float qscale = 0.08838834764831845f;
#pragma unroll
        for (int mt = 0; mt < 2; mt++) {
            int m = m0 + wm * 32 + mt * 16 + gid;
            int bb = m >> 11, tt = m & 2047;
#pragma unroll
            for (int nt = 0; nt < 8; nt++) {
                int n = n0 + wn * 64 + nt * 8 + tig * 2;
                int tens = n >> 11;
                int dcol = n & 2047;
                int hh = dcol >> 7, hd = dcol & 127;
                size_t idx = (((size_t)(bb * 16 + hh)) * 2048 + tt) * 128 + hd;
                float sc = (tens == 0) ? qscale : 1.0f;
                uint32_t h0, l0, h1, l1;
                split2(acc[mt][nt][0] * sc, acc[mt][nt][1] * sc, h0, l0);
                split2(acc[mt][nt][2] * sc, acc[mt][nt][3] * sc, h1, l1);
                __nv_bfloat16 *dh, *dl;
                if (tens == 0)      { dh = qh_o; dl = ql_o; }
                else if (tens == 1) { dh = kh_o; dl = kl_o; }
                else                { dh = vh_o; dl = vl_o; }
                *(uint32_t*)(dh + idx) = h0;
                *(uint32_t*)(dl + idx) = l0;
                *(uint32_t*)(dh + idx + 8 * 128) = h1;
                *(uint32_t*)(dl + idx + 8 * 128) = l1;
            }
        }
    }
}

// ============================================================================
// HMMA causal flash attention — EXACT R9 structure (proven ~356 us)
// ============================================================================
#define AST 152
#define STG (64 * AST)
#define FL_STAGE (4 * STG)
#define FL_SMEM_BYTES (2 * FL_STAGE * 2)

__global__ __launch_bounds__(256)
void flash_hmma2(const __nv_bfloat16* __restrict__ QH, const __nv_bfloat16* __restrict__ QL,
                 const __nv_bfloat16* __restrict__ KHg, const __nv_bfloat16* __restrict__ KLg,
                 const __nv_bfloat16* __restrict__ VHg, const __nv_bfloat16* __restrict__ VLg,
                 __nv_bfloat16* __restrict__ OH, __nv_bfloat16* __restrict__ OL)
{
    extern __shared__ __nv_bfloat16 asm_[];
    const uint32_t smb = smem_u32_of(asm_);

    const int qb  = blockIdx.x;
    const int bh  = blockIdx.y;
    const int b   = bh >> 4;
    const int h   = bh & 15;
    const int tid = threadIdx.x;
    const int wid = tid >> 5;
    const int lid = tid & 31;
    const int gid = lid >> 2;
    const int tig = lid & 3;

    const size_t hb = (size_t)bh * T_ * HD_;

    const int r0 = qb * 128 + wid * 16 + gid;
    uint32_t qh[8][4], ql[8][4];
    {
        const __nv_bfloat16* q0h = QH + hb + (size_t)r0 * HD_;
        const __nv_bfloat16* q1h = QH + hb + (size_t)(r0 + 8) * HD_;
        const __nv_bfloat16* q0l = QL + hb + (size_t)r0 * HD_;
        const __nv_bfloat16* q1l = QL + hb + (size_t)(r0 + 8) * HD_;
#pragma unroll
        for (int kc = 0; kc < 8; kc++) {
            int c = kc * 16 + 2 * tig;
            qh[kc][0] = *(const uint32_t*)(q0h + c);
            qh[kc][1] = *(const uint32_t*)(q1h + c);
            qh[kc][2] = *(const uint32_t*)(q0h + c + 8);
            qh[kc][3] = *(const uint32_t*)(q1h + c + 8);
            ql[kc][0] = *(const uint32_t*)(q0l + c);
            ql[kc][1] = *(const uint32_t*)(q1l + c);
            ql[kc][2] = *(const uint32_t*)(q0l + c + 8);
            ql[kc][3] = *(const uint32_t*)(q1l + c + 8);
        }
    }

    float m0 = -1e30f, m1 = -1e30f, l0 = 0.f, l1 = 0.f;
    float o[16][4];
#pragma unroll
    for (int i = 0; i < 16; i++)
#pragma unroll
        for (int r = 0; r < 4; r++) o[i][r] = 0.f;

    const int lu = tid & 63;
    const int la = tid >> 6;
    const __nv_bfloat16* lg =
        (la == 0) ? (KHg + hb) : (la == 1) ? (KLg + hb)
      : (la == 2) ? (VHg + hb) : (VLg + hb);

    const uint32_t lmoff = (uint32_t)(((lid & 7) * AST + (lid >> 3) * 8) * 2);
    const uint32_t voff  = (uint32_t)(((lid & 15) * AST + (lid >> 4) * 8) * 2);

    const int ntiles = 2 * qb + 2;

    {
        uint32_t sd = smb + (uint32_t)(la * STG) * 2;
#pragma unroll
        for (int i = 0; i < 16; i++) {
            int cid = lu + 64 * i;
            int row = cid >> 4, col = cid & 15;
            cp16(sd + (uint32_t)(row * AST + col * 8) * 2,
                 lg + (size_t)row * HD_ + col * 8);
        }
    }
    CP_COMMIT();

    for (int kb = 0; kb < ntiles; kb++) {
        CP_WAIT0();
        __syncthreads();

        if (kb + 1 < ntiles) {
            uint32_t sd = smb + (uint32_t)(((kb + 1) & 1) * FL_STAGE + la * STG) * 2;
            const __nv_bfloat16* gs = lg + (size_t)((kb + 1) * 64) * HD_;
#pragma unroll
            for (int i = 0; i < 16; i++) {
                int cid = lu + 64 * i;
                int row = cid >> 4, col = cid & 15;
                cp16(sd + (uint32_t)(row * AST + col * 8) * 2,
                     gs + (size_t)row * HD_ + col * 8);
            }
            CP_COMMIT();
        }

        if (kb * 64 > qb * 128 + wid * 16 + 15) continue;

        const int st = kb & 1;
        const uint32_t kh_s = smb + (uint32_t)(st * FL_STAGE) * 2;
        const uint32_t kl_s = kh_s + (uint32_t)STG * 2;
        const uint32_t vh_s = kh_s + (uint32_t)(2 * STG) * 2;
        const uint32_t vl_s = kh_s + (uint32_t)(3 * STG) * 2;

        float s[8][4];
#pragma unroll
        for (int nt = 0; nt < 8; nt++)
#pragma unroll
            for (int r = 0; r < 4; r++) s[nt][r] = 0.f;

#pragma unroll
        for (int kcp = 0; kcp < 4; kcp++) {
#pragma unroll
            for (int nt = 0; nt < 8; nt++) {
                uint32_t off = (uint32_t)(nt * 8 * AST * 2 + kcp * 64) + lmoff;
                uint32_t bh4[4], bl4[4];
                ldmx4(bh4, kh_s + off);
                ldmx4(bl4, kl_s + off);
                mma16816(s[nt], qh[2 * kcp],     bh4);
                mma16816(s[nt], qh[2 * kcp],     bl4);
                mma16816(s[nt], ql[2 * kcp],     bh4);
                mma16816(s[nt], qh[2 * kcp + 1], bh4 + 2);
                mma16816(s[nt], qh[2 * kcp + 1], bl4 + 2);
                mma16816(s[nt], ql[2 * kcp + 1], bh4 + 2);
            }
        }

        if (kb * 64 + 63 > qb * 128 + wid * 16) {
            const int rr0 = r0, rr1 = r0 + 8;
#pragma unroll
            for (int nt = 0; nt < 8; nt++) {
                int c0 = kb * 64 + nt * 8 + 2 * tig;
                int c1 = c0 + 1;
                if (c0 > rr0) s[nt][0] = -1e30f;
                if (c1 > rr0) s[nt][1] = -1e30f;
                if (c0 > rr1) s[nt][2] = -1e30f;
                if (c1 > rr1) s[nt][3] = -1e30f;
            }
        }

        float mx0 = -1e30f, mx1 = -1e30f;
#pragma unroll
        for (int nt = 0; nt < 8; nt++) {
            mx0 = fmaxf(mx0, fmaxf(s[nt][0], s[nt][1]));
            mx1 = fmaxf(mx1, fmaxf(s[nt][2], s[nt][3]));
        }
        mx0 = fmaxf(mx0, __shfl_xor_sync(0xFFFFFFFF, mx0, 1));
        mx0 = fmaxf(mx0, __shfl_xor_sync(0xFFFFFFFF, mx0, 2));
        mx1 = fmaxf(mx1, __shfl_xor_sync(0xFFFFFFFF, mx1, 1));
        mx1 = fmaxf(mx1, __shfl_xor_sync(0xFFFFFFFF, mx1, 2));
        float mn0 = fmaxf(m0, mx0), mn1 = fmaxf(m1, mx1);
        float a0 = __expf(m0 - mn0), a1 = __expf(m1 - mn1);
        m0 = mn0; m1 = mn1;

        float ps0 = 0.f, ps1 = 0.f;
#pragma unroll
        for (int nt = 0; nt < 8; nt++) {
            s[nt][0] = __expf(s[nt][0] - mn0); ps0 += s[nt][0];
            s[nt][1] = __expf(s[nt][1] - mn0); ps0 += s[nt][1];
            s[nt][2] = __expf(s[nt][2] - mn1); ps1 += s[nt][2];
            s[nt][3] = __expf(s[nt][3] - mn1); ps1 += s[nt][3];
        }
        ps0 += __shfl_xor_sync(0xFFFFFFFF, ps0, 1);
        ps0 += __shfl_xor_sync(0xFFFFFFFF, ps0, 2);
        ps1 += __shfl_xor_sync(0xFFFFFFFF, ps1, 1);
        ps1 += __shfl_xor_sync(0xFFFFFFFF, ps1, 2);
        l0 = l0 * a0 + ps0;
        l1 = l1 * a1 + ps1;

#pragma unroll
        for (int nt = 0; nt < 16; nt++) {
            o[nt][0] *= a0; o[nt][1] *= a0;
            o[nt][2] *= a1; o[nt][3] *= a1;
        }

#pragma unroll
        for (int kt = 0; kt < 4; kt++) {
            uint32_t aph[4], apl[4];
            split2(s[2 * kt][0],     s[2 * kt][1],     aph[0], apl[0]);
            split2(s[2 * kt][2],     s[2 * kt][3],     aph[1], apl[1]);
            split2(s[2 * kt + 1][0], s[2 * kt + 1][1], aph[2], apl[2]);
            split2(s[2 * kt + 1][2], s[2 * kt + 1][3], aph[3], apl[3]);
            const uint32_t ktoff = (uint32_t)(kt * 16 * AST * 2);
#pragma unroll
            for (int ntp = 0; ntp < 8; ntp++) {
                uint32_t vh4[4], vl4[4];
                uint32_t off = ktoff + (uint32_t)(ntp * 32) + voff;
                ldmx4t(vh4, vh_s + off);
                ldmx4t(vl4, vl_s + off);
                mma16816(o[2 * ntp],     aph, vh4);
                mma16816(o[2 * ntp],     aph, vl4);
                mma16816(o[2 * ntp],     apl, vh4);
                mma16816(o[2 * ntp + 1], aph, vh4 + 2);
                mma16816(o[2 * ntp + 1], aph, vl4 + 2);
                mma16816(o[2 * ntp + 1], apl, vh4 + 2);
            }
        }
    }

    // ---- normalize + write pre-split bf16 [B,T,D]
    float il0 = 1.f / l0, il1 = 1.f / l1;
    size_t base0 = ((size_t)b * T_ + r0) * D_ + h * HD_;
    size_t base1 = ((size_t)b * T_ + r0 + 8) * D_ + h * HD_;
#pragma unroll
    for (int nt = 0; nt < 16; nt++) {
        uint32_t h0, lo0, h1, lo1;
        split2(o[nt][0] * il0, o[nt][1] * il0, h0, lo0);
        split2(o[nt][2] * il1, o[nt][3] * il1, h1, lo1);
        size_t c = nt * 8 + 2 * tig;
        *(uint32_t*)(OH + base0 + c) = h0;
        *(uint32_t*)(OL + base0 + c) = lo0;
        *(uint32_t*)(OH + base1 + c) = h1;
        *(uint32_t*)(OL + base1 + c) = lo1;
    }
}

// ---------------------------------------------------------------------------
extern "C" void kernel_launch(void* const* d_in, const int* in_sizes, int n_in,
                              void* d_out, int out_size)
{
    (void)in_sizes; (void)n_in; (void)out_size;
    const float* x    = (const float*)d_in[0];
    const float* wqkv = (const float*)d_in[2];
    const float* wout = (const float*)d_in[3];
    const float* bout = (const float*)d_in[4];
    float* outp = (float*)d_out;

    __nv_bfloat16 *qh_p, *ql_p, *kh_p, *kl_p, *vh_p, *vl_p;
    __nv_bfloat16 *xh_p, *xl_p, *w1h_p, *w1l_p, *w2h_p, *w2l_p, *ah_p, *al_p;
    cudaGetSymbolAddress((void**)&qh_p, g_qh);
    cudaGetSymbolAddress((void**)&ql_p, g_ql);
    cudaGetSymbolAddress((void**)&kh_p, g_kh);
    cudaGetSymbolAddress((void**)&kl_p, g_kl);
    cudaGetSymbolAddress((void**)&vh_p, g_vh);
    cudaGetSymbolAddress((void**)&vl_p, g_vl);
    cudaGetSymbolAddress((void**)&xh_p, g_xh);
    cudaGetSymbolAddress((void**)&xl_p, g_xl);
    cudaGetSymbolAddress((void**)&w1h_p, g_w1h);
    cudaGetSymbolAddress((void**)&w1l_p, g_w1l);
    cudaGetSymbolAddress((void**)&w2h_p, g_w2h);
    cudaGetSymbolAddress((void**)&w2l_p, g_w2l);
    cudaGetSymbolAddress((void**)&ah_p, g_ah);
    cudaGetSymbolAddress((void**)&al_p, g_al);

    cudaFuncSetAttribute(gemm_bf16<1>,
                         cudaFuncAttributeMaxDynamicSharedMemorySize, G_SMEM_BYTES);
    cudaFuncSetAttribute(gemm_bf16<2>,
                         cudaFuncAttributeMaxDynamicSharedMemorySize, G_SMEM_BYTES);
    cudaFuncSetAttribute(flash_hmma2,
                         cudaFuncAttributeMaxDynamicSharedMemorySize, FL_SMEM_BYTES);

    // 0) split inputs into bf16 hi/lo
    split_f32<<<592, 256>>>(x,    xh_p,  xl_p,  (B_ * T_ * D_) / 4);
    split_f32<<<592, 256>>>(wqkv, w1h_p, w1l_p, (3 * D_ * D_) / 4);
    split_f32<<<592, 256>>>(wout, w2h_p, w2l_p, (D_ * D_) / 4);

    // 1) QKV projection + fused split/scale epilogue (512-thread CTAs)
    dim3 g1((3 * D_) / 128, (B_ * T_) / 256);
    gemm_bf16<2><<<g1, 512, G_SMEM_BYTES>>>(xh_p, xl_p, w1h_p, w1l_p,
                                            nullptr, nullptr,
                                            qh_p, ql_p, kh_p, kl_p, vh_p, vl_p,
                                            B_ * T_, 3 * D_, D_);

    // 2) causal flash attention -> pre-split bf16 output
    dim3 g2(T_ / 128, B_ * H_);
    flash_hmma2<<<g2, 256, FL_SMEM_BYTES>>>(qh_p, ql_p, kh_p, kl_p, vh_p, vl_p,
                                            ah_p, al_p);

    // 3) output projection + bias (512-thread CTAs)
    dim3 g3(D_ / 128, (B_ * T_) / 256);
    gemm_bf16<1><<<g3, 512, G_SMEM_BYTES>>>(ah_p, al_p, w2h_p, w2l_p,
                                            bout, outp,
                                            nullptr, nullptr, nullptr, nullptr,
                                            nullptr, nullptr,
                                            B_ * T_, D_, D_);
}

// round 15
// speedup vs baseline: 1.7524x; 1.1587x over previous
#include <cuda_runtime.h>
#include <cuda_bf16.h>
#include <cstdint>

#define B_  2
#define T_  2048
#define D_  2048
#define H_  16
#define HD_ 128

// Scratch (no cudaMalloc): pre-split bf16 operands everywhere
#define QKVN ((size_t)B_ * H_ * T_ * HD_)
__device__ __nv_bfloat16 g_qh[QKVN], g_ql[QKVN];
__device__ __nv_bfloat16 g_kh[QKVN], g_kl[QKVN];
__device__ __nv_bfloat16 g_vh[QKVN], g_vl[QKVN];
__device__ __nv_bfloat16 g_xh[(size_t)B_ * T_ * D_],  g_xl[(size_t)B_ * T_ * D_];
__device__ __nv_bfloat16 g_w1h[(size_t)3 * D_ * D_],  g_w1l[(size_t)3 * D_ * D_];
__device__ __nv_bfloat16 g_w2h[(size_t)D_ * D_],      g_w2l[(size_t)D_ * D_];
__device__ __nv_bfloat16 g_ah[(size_t)B_ * T_ * D_],  g_al[(size_t)B_ * T_ * D_];

// ============================================================================
// Helpers
// ============================================================================
__device__ __forceinline__ void mma16816(float* c, const uint32_t* a, const uint32_t* b) {
    asm volatile(
        "mma.sync.aligned.m16n8k16.row.col.f32.bf16.bf16.f32 "
        "{%0,%1,%2,%3}, {%4,%5,%6,%7}, {%8,%9}, {%0,%1,%2,%3};"
        : "+f"(c[0]), "+f"(c[1]), "+f"(c[2]), "+f"(c[3])
        : "r"(a[0]), "r"(a[1]), "r"(a[2]), "r"(a[3]), "r"(b[0]), "r"(b[1]));
}
__device__ __forceinline__ uint32_t bf2_bits(__nv_bfloat162 h) {
    uint32_t u; *reinterpret_cast<__nv_bfloat162*>(&u) = h; return u;
}
__device__ __forceinline__ void split2(float x, float y, uint32_t& hi, uint32_t& lo) {
    __nv_bfloat162 h = __floats2bfloat162_rn(x, y);
    __nv_bfloat162 l = __floats2bfloat162_rn(x - __low2float(h), y - __high2float(h));
    hi = bf2_bits(h); lo = bf2_bits(l);
}
__device__ __forceinline__ void split4(float4 v, uint2& hi, uint2& lo) {
    __nv_bfloat162 h0 = __floats2bfloat162_rn(v.x, v.y);
    __nv_bfloat162 h1 = __floats2bfloat162_rn(v.z, v.w);
    __nv_bfloat162 l0 = __floats2bfloat162_rn(v.x - __low2float(h0), v.y - __high2float(h0));
    __nv_bfloat162 l1 = __floats2bfloat162_rn(v.z - __low2float(h1), v.w - __high2float(h1));
    hi = make_uint2(bf2_bits(h0), bf2_bits(h1));
    lo = make_uint2(bf2_bits(l0), bf2_bits(l1));
}
__device__ __forceinline__ uint32_t smem_u32_of(const void* p) {
    uint32_t a;
    asm("{ .reg .u64 t; cvta.to.shared.u64 t, %1; cvt.u32.u64 %0, t; }"
        : "=r"(a) : "l"(p));
    return a;
}
__device__ __forceinline__ void ldmx4t(uint32_t* r, uint32_t saddr) {
    asm volatile("ldmatrix.sync.aligned.m8n8.x4.trans.shared.b16 {%0,%1,%2,%3}, [%4];"
                 : "=r"(r[0]), "=r"(r[1]), "=r"(r[2]), "=r"(r[3]) : "r"(saddr));
}
__device__ __forceinline__ void ldmx4(uint32_t* r, uint32_t saddr) {
    asm volatile("ldmatrix.sync.aligned.m8n8.x4.shared.b16 {%0,%1,%2,%3}, [%4];"
                 : "=r"(r[0]), "=r"(r[1]), "=r"(r[2]), "=r"(r[3]) : "r"(saddr));
}
__device__ __forceinline__ void ldmx2(uint32_t* r, uint32_t saddr) {
    asm volatile("ldmatrix.sync.aligned.m8n8.x2.shared.b16 {%0,%1}, [%2];"
                 : "=r"(r[0]), "=r"(r[1]) : "r"(saddr));
}
__device__ __forceinline__ void cp16(uint32_t d, const void* s) {
    asm volatile("cp.async.cg.shared.global [%0], [%1], 16;" :: "r"(d), "l"(s) : "memory");
}
#define CP_COMMIT() asm volatile("cp.async.commit_group;" ::: "memory")
#define CP_WAIT0()  asm volatile("cp.async.wait_group 0;" ::: "memory")

// ============================================================================
// fp32 -> bf16 hi/lo split kernel
// ============================================================================
__global__ __launch_bounds__(256)
void split_f32(const float* __restrict__ src, __nv_bfloat16* __restrict__ hi,
               __nv_bfloat16* __restrict__ lo, int n4)
{
    for (int i = blockIdx.x * blockDim.x + threadIdx.x; i < n4;
         i += gridDim.x * blockDim.x) {
        float4 v = reinterpret_cast<const float4*>(src)[i];
        uint2 h, l;
        split4(v, h, l);
        reinterpret_cast<uint2*>(hi)[i] = h;
        reinterpret_cast<uint2*>(lo)[i] = l;
    }
}

// ============================================================================
// All-bf16 pre-split NT GEMM. KC=64, 2-stage (221 KB smem), 256 threads,
// 8 warps (4m x 2n), warp tile 64x64 -> 384 MMA/warp/iteration (flash cadence).
// cp.async issue burst overlapped inside the compute phase.
// ============================================================================
#define ARP2  72                          // bf16 row stride (144 B, conflict-free)
#define KCH2  64
#define A_ST2 (256 * ARP2)                // 18432 elems
#define B_ST2 (128 * ARP2)                // 9216 elems
#define ST2   (2 * A_ST2 + 2 * B_ST2)     // 55296 elems / stage
#define G2_SMEM_BYTES (2 * ST2 * 2)       // 221184 B

template <int MODE>
__global__ __launch_bounds__(256)
void gemm_bf16(const __nv_bfloat16* __restrict__ Ah, const __nv_bfloat16* __restrict__ Al,
               const __nv_bfloat16* __restrict__ Bh, const __nv_bfloat16* __restrict__ Bl,
               const float* __restrict__ bias, float* __restrict__ C,
               __nv_bfloat16* __restrict__ qh_o, __nv_bfloat16* __restrict__ ql_o,
               __nv_bfloat16* __restrict__ kh_o, __nv_bfloat16* __restrict__ kl_o,
               __nv_bfloat16* __restrict__ vh_o, __nv_bfloat16* __restrict__ vl_o,
               int M, int N, int K)
{
    extern __shared__ __nv_bfloat16 smem[];
    const uint32_t smb = smem_u32_of(smem);

    const int tid = threadIdx.x;
    const int wid = tid >> 5;
    const int lid = tid & 31;
    const int gid = lid >> 2;
    const int tig = lid & 3;
    const int wm  = wid >> 1;          // 0..3 (64-row slabs)
    const int wn  = wid & 1;           // 0..1 (64-col slabs)
    const int m0  = blockIdx.y * 256;
    const int n0  = blockIdx.x * 128;

    const __nv_bfloat16* Ahb = Ah + (size_t)m0 * K;
    const __nv_bfloat16* Alb = Al + (size_t)m0 * K;
    const __nv_bfloat16* Bhb = Bh + (size_t)n0 * K;
    const __nv_bfloat16* Blb = Bl + (size_t)n0 * K;

    float acc[4][8][4];
#pragma unroll
    for (int i = 0; i < 4; i++)
#pragma unroll
        for (int j = 0; j < 8; j++)
#pragma unroll
            for (int r = 0; r < 4; r++) acc[i][j][r] = 0.f;

    const int NC = K / KCH2;           // 32

    // loader: 24 cp16/thread per stage (A hi/lo: 8+8, B hi/lo: 4+4)
    auto load_stage = [&](int ks, int slot) {
        const int k0 = ks * KCH2;
        const uint32_t sb = smb + (uint32_t)(slot * ST2) * 2;
#pragma unroll
        for (int u = 0; u < 8; u++) {
            int s = tid + u * 256;
            int row = s >> 3, ch = s & 7;
            uint32_t d = sb + (uint32_t)(row * ARP2 + ch * 8) * 2;
            cp16(d, Ahb + (size_t)row * K + k0 + ch * 8);
            cp16(d + (uint32_t)A_ST2 * 2, Alb + (size_t)row * K + k0 + ch * 8);
        }
#pragma unroll
        for (int u = 0; u < 4; u++) {
            int s = tid + u * 256;
            int row = s >> 3, ch = s & 7;
            uint32_t d = sb + (uint32_t)(2 * A_ST2 + row * ARP2 + ch * 8) * 2;
            cp16(d, Bhb + (size_t)row * K + k0 + ch * 8);
            cp16(d + (uint32_t)B_ST2 * 2, Blb + (size_t)row * K + k0 + ch * 8);
        }
    };

    load_stage(0, 0);
    CP_COMMIT();

    const int a_lane = (lid & 15) * ARP2 + (lid >> 4) * 8;
    const int b_lane = (lid & 7) * ARP2 + ((lid >> 3) & 1) * 8;

    for (int i = 0; i < NC; i++) {
        CP_WAIT0();                     // only stage-i group outstanding here
        __syncthreads();                // stage i visible to all; prev compute done

        const uint32_t sb   = smb + (uint32_t)((i & 1) * ST2) * 2;
        const uint32_t sbAh = sb;
        const uint32_t sbAl = sb + (uint32_t)A_ST2 * 2;
        const uint32_t sbBh = sb + (uint32_t)(2 * A_ST2) * 2;
        const uint32_t sbBl = sb + (uint32_t)(2 * A_ST2 + B_ST2) * 2;

        // compute kc=0,1
#pragma unroll
        for (int kc = 0; kc < 2; kc++) {
            uint32_t ah[4][4], al[4][4];
#pragma unroll
            for (int mt = 0; mt < 4; mt++) {
                uint32_t off = (uint32_t)(((wm * 64 + mt * 16) * ARP2 + kc * 16 + a_lane) * 2);
                ldmx4(ah[mt], sbAh + off);
                ldmx4(al[mt], sbAl + off);
            }
#pragma unroll
            for (int ng = 0; ng < 8; ng++) {
                uint32_t off = (uint32_t)(((wn * 64 + ng * 8) * ARP2 + kc * 16 + b_lane) * 2);
                uint32_t bh2[2], bl2[2];
                ldmx2(bh2, sbBh + off);
                ldmx2(bl2, sbBl + off);
#pragma unroll
                for (int mt = 0; mt < 4; mt++) {
                    mma16816(acc[mt][ng], ah[mt], bh2);
                    mma16816(acc[mt][ng], ah[mt], bl2);
                    mma16816(acc[mt][ng], al[mt], bh2);
                }
            }
        }

        // overlapped prefetch of stage i+1 into the other slot
        if (i + 1 < NC) load_stage(i + 1, (i + 1) & 1);
        CP_COMMIT();

        // compute kc=2,3
#pragma unroll
        for (int kc = 2; kc < 4; kc++) {
            uint32_t ah[4][4], al[4][4];
#pragma unroll
            for (int mt = 0; mt < 4; mt++) {
                uint32_t off = (uint32_t)(((wm * 64 + mt * 16) * ARP2 + kc * 16 + a_lane) * 2);
                ldmx4(ah[mt], sbAh + off);
                ldmx4(al[mt], sbAl + off);
            }
#pragma unroll
            for (int ng = 0; ng < 8; ng++) {
                uint32_t off = (uint32_t)(((wn * 64 + ng * 8) * ARP2 + kc * 16 + b_lane) * 2);
                uint32_t bh2[2], bl2[2];
                ldmx2(bh2, sbBh + off);
                ldmx2(bl2, sbBl + off);
#pragma unroll
                for (int mt = 0; mt < 4; mt++) {
                    mma16816(acc[mt][ng], ah[mt], bh2);
                    mma16816(acc[mt][ng], ah[mt], bl2);
                    mma16816(acc[mt][ng], al[mt], bh2);
                }
            }
        }

        __syncthreads();                // close WAR window on the other slot
    }

    if (MODE == 1) {
#pragma unroll
        for (int mt = 0; mt < 4; mt++) {
            int m = m0 + wm * 64 + mt * 16 + gid;
#pragma unroll
            for (int nt = 0; nt < 8; nt++) {
                int n = n0 + wn * 64 + nt * 8 + tig * 2;
                float2 v0 = make_float2(acc[mt][nt][0], acc[mt][nt][1]);
                float2 v1 = make_float2(acc[mt][nt][2], acc[mt][nt][3]);
                float b0 = bias[n], b1 = bias[n + 1];
                v0.x += b0; v0.y += b1;
                v1.x += b0; v1.y += b1;
                *(float2*)(C + (size_t)m * N + n)       = v0;
                *(float2*)(C + (size_t)(m + 8) * N + n) = v1;
            }
        }
    } else {
        const float qscale = 0.08838834764831845f;
#pragma unroll
        for (int mt = 0; mt < 4; mt++) {
            int m = m0 + wm * 64 + mt * 16 + gid;
            int bb = m >> 11, tt = m & 2047;
#pragma unroll
            for (int nt = 0; nt < 8; nt++) {
                int n = n0 + wn * 64 + nt * 8 + tig * 2;
                int tens = n >> 11;
                int dcol = n & 2047;
                int hh = dcol >> 7, hd = dcol & 127;
                size_t idx = (((size_t)(bb * 16 + hh)) * 2048 + tt) * 128 + hd;
                float sc = (tens == 0) ? qscale : 1.0f;
                uint32_t h0, l0, h1, l1;
                split2(acc[mt][nt][0] * sc, acc[mt][nt][1] * sc, h0, l0);
                split2(acc[mt][nt][2] * sc, acc[mt][nt][3] * sc, h1, l1);
                __nv_bfloat16 *dh, *dl;
                if (tens == 0)      { dh = qh_o; dl = ql_o; }
                else if (tens == 1) { dh = kh_o; dl = kl_o; }
                else                { dh = vh_o; dl = vl_o; }
                *(uint32_t*)(dh + idx) = h0;
                *(uint32_t*)(dl + idx) = l0;
                *(uint32_t*)(dh + idx + 8 * 128) = h1;
                *(uint32_t*)(dl + idx + 8 * 128) = l1;
            }
        }
    }
}

// ============================================================================
// HMMA causal flash attention — EXACT R9 structure (proven ~356 us)
// ============================================================================
#define AST 152
#define STG (64 * AST)
#define FL_STAGE (4 * STG)
#define FL_SMEM_BYTES (2 * FL_STAGE * 2)

__global__ __launch_bounds__(256)
void flash_hmma2(const __nv_bfloat16* __restrict__ QH, const __nv_bfloat16* __restrict__ QL,
                 const __nv_bfloat16* __restrict__ KHg, const __nv_bfloat16* __restrict__ KLg,
                 const __nv_bfloat16* __restrict__ VHg, const __nv_bfloat16* __restrict__ VLg,
                 __nv_bfloat16* __restrict__ OH, __nv_bfloat16* __restrict__ OL)
{
    extern __shared__ __nv_bfloat16 asm_[];
    const uint32_t smb = smem_u32_of(asm_);

    const int qb  = blockIdx.x;
    const int bh  = blockIdx.y;
    const int b   = bh >> 4;
    const int h   = bh & 15;
    const int tid = threadIdx.x;
    const int wid = tid >> 5;
    const int lid = tid & 31;
    const int gid = lid >> 2;
    const int tig = lid & 3;

    const size_t hb = (size_t)bh * T_ * HD_;

    const int r0 = qb * 128 + wid * 16 + gid;
    uint32_t qh[8][4], ql[8][4];
    {
        const __nv_bfloat16* q0h = QH + hb + (size_t)r0 * HD_;
        const __nv_bfloat16* q1h = QH + hb + (size_t)(r0 + 8) * HD_;
        const __nv_bfloat16* q0l = QL + hb + (size_t)r0 * HD_;
        const __nv_bfloat16* q1l = QL + hb + (size_t)(r0 + 8) * HD_;
#pragma unroll
        for (int kc = 0; kc < 8; kc++) {
            int c = kc * 16 + 2 * tig;
            qh[kc][0] = *(const uint32_t*)(q0h + c);
            qh[kc][1] = *(const uint32_t*)(q1h + c);
            qh[kc][2] = *(const uint32_t*)(q0h + c + 8);
            qh[kc][3] = *(const uint32_t*)(q1h + c + 8);
            ql[kc][0] = *(const uint32_t*)(q0l + c);
            ql[kc][1] = *(const uint32_t*)(q1l + c);
            ql[kc][2] = *(const uint32_t*)(q0l + c + 8);
            ql[kc][3] = *(const uint32_t*)(q1l + c + 8);
        }
    }

    float m0 = -1e30f, m1 = -1e30f, l0 = 0.f, l1 = 0.f;
    float o[16][4];
#pragma unroll
    for (int i = 0; i < 16; i++)
#pragma unroll
        for (int r = 0; r < 4; r++) o[i][r] = 0.f;

    const int lu = tid & 63;
    const int la = tid >> 6;
    const __nv_bfloat16* lg =
        (la == 0) ? (KHg + hb) : (la == 1) ? (KLg + hb)
      : (la == 2) ? (VHg + hb) : (VLg + hb);

    const uint32_t lmoff = (uint32_t)(((lid & 7) * AST + (lid >> 3) * 8) * 2);
    const uint32_t voff  = (uint32_t)(((lid & 15) * AST + (lid >> 4) * 8) * 2);

    const int ntiles = 2 * qb + 2;

    {
        uint32_t sd = smb + (uint32_t)(la * STG) * 2;
#pragma unroll
        for (int i = 0; i < 16; i++) {
            int cid = lu + 64 * i;
            int row = cid >> 4, col = cid & 15;
            cp16(sd + (uint32_t)(row * AST + col * 8) * 2,
                 lg + (size_t)row * HD_ + col * 8);
        }
    }
    CP_COMMIT();

    for (int kb = 0; kb < ntiles; kb++) {
        CP_WAIT0();
        __syncthreads();

        if (kb + 1 < ntiles) {
            uint32_t sd = smb + (uint32_t)(((kb + 1) & 1) * FL_STAGE + la * STG) * 2;
            const __nv_bfloat16* gs = lg + (size_t)((kb + 1) * 64) * HD_;
#pragma unroll
            for (int i = 0; i < 16; i++) {
                int cid = lu + 64 * i;
                int row = cid >> 4, col = cid & 15;
                cp16(sd + (uint32_t)(row * AST + col * 8) * 2,
                     gs + (size_t)row * HD_ + col * 8);
            }
            CP_COMMIT();
        }

        if (kb * 64 > qb * 128 + wid * 16 + 15) continue;

        const int st = kb & 1;
        const uint32_t kh_s = smb + (uint32_t)(st * FL_STAGE) * 2;
        const uint32_t kl_s = kh_s + (uint32_t)STG * 2;
        const uint32_t vh_s = kh_s + (uint32_t)(2 * STG) * 2;
        const uint32_t vl_s = kh_s + (uint32_t)(3 * STG) * 2;

        float s[8][4];
#pragma unroll
        for (int nt = 0; nt < 8; nt++)
#pragma unroll
            for (int r = 0; r < 4; r++) s[nt][r] = 0.f;

#pragma unroll
        for (int kcp = 0; kcp < 4; kcp++) {
#pragma unroll
            for (int nt = 0; nt < 8; nt++) {
                uint32_t off = (uint32_t)(nt * 8 * AST * 2 + kcp * 64) + lmoff;
                uint32_t bh4[4], bl4[4];
                ldmx4(bh4, kh_s + off);
                ldmx4(bl4, kl_s + off);
                mma16816(s[nt], qh[2 * kcp],     bh4);
                mma16816(s[nt], qh[2 * kcp],     bl4);
                mma16816(s[nt], ql[2 * kcp],     bh4);
                mma16816(s[nt], qh[2 * kcp + 1], bh4 + 2);
                mma16816(s[nt], qh[2 * kcp + 1], bl4 + 2);
                mma16816(s[nt], ql[2 * kcp + 1], bh4 + 2);
            }
        }

        if (kb * 64 + 63 > qb * 128 + wid * 16) {
            const int rr0 = r0, rr1 = r0 + 8;
#pragma unroll
            for (int nt = 0; nt < 8; nt++) {
                int c0 = kb * 64 + nt * 8 + 2 * tig;
                int c1 = c0 + 1;
                if (c0 > rr0) s[nt][0] = -1e30f;
                if (c1 > rr0) s[nt][1] = -1e30f;
                if (c0 > rr1) s[nt][2] = -1e30f;
                if (c1 > rr1) s[nt][3] = -1e30f;
            }
        }

        float mx0 = -1e30f, mx1 = -1e30f;
#pragma unroll
        for (int nt = 0; nt < 8; nt++) {
            mx0 = fmaxf(mx0, fmaxf(s[nt][0], s[nt][1]));
            mx1 = fmaxf(mx1, fmaxf(s[nt][2], s[nt][3]));
        }
        mx0 = fmaxf(mx0, __shfl_xor_sync(0xFFFFFFFF, mx0, 1));
        mx0 = fmaxf(mx0, __shfl_xor_sync(0xFFFFFFFF, mx0, 2));
        mx1 = fmaxf(mx1, __shfl_xor_sync(0xFFFFFFFF, mx1, 1));
        mx1 = fmaxf(mx1, __shfl_xor_sync(0xFFFFFFFF, mx1, 2));
        float mn0 = fmaxf(m0, mx0), mn1 = fmaxf(m1, mx1);
        float a0 = __expf(m0 - mn0), a1 = __expf(m1 - mn1);
        m0 = mn0; m1 = mn1;

        float ps0 = 0.f, ps1 = 0.f;
#pragma unroll
        for (int nt = 0; nt < 8; nt++) {
            s[nt][0] = __expf(s[nt][0] - mn0); ps0 += s[nt][0];
            s[nt][1] = __expf(s[nt][1] - mn0); ps0 += s[nt][1];
            s[nt][2] = __expf(s[nt][2] - mn1); ps1 += s[nt][2];
            s[nt][3] = __expf(s[nt][3] - mn1); ps1 += s[nt][3];
        }
        ps0 += __shfl_xor_sync(0xFFFFFFFF, ps0, 1);
        ps0 += __shfl_xor_sync(0xFFFFFFFF, ps0, 2);
        ps1 += __shfl_xor_sync(0xFFFFFFFF, ps1, 1);
        ps1 += __shfl_xor_sync(0xFFFFFFFF, ps1, 2);
        l0 = l0 * a0 + ps0;
        l1 = l1 * a1 + ps1;

#pragma unroll
        for (int nt = 0; nt < 16; nt++) {
            o[nt][0] *= a0; o[nt][1] *= a0;
            o[nt][2] *= a1; o[nt][3] *= a1;
        }

#pragma unroll
        for (int kt = 0; kt < 4; kt++) {
            uint32_t aph[4], apl[4];
            split2(s[2 * kt][0],     s[2 * kt][1],     aph[0], apl[0]);
            split2(s[2 * kt][2],     s[2 * kt][3],     aph[1], apl[1]);
            split2(s[2 * kt + 1][0], s[2 * kt + 1][1], aph[2], apl[2]);
            split2(s[2 * kt + 1][2], s[2 * kt + 1][3], aph[3], apl[3]);
            const uint32_t ktoff = (uint32_t)(kt * 16 * AST * 2);
#pragma unroll
            for (int ntp = 0; ntp < 8; ntp++) {
                uint32_t vh4[4], vl4[4];
                uint32_t off = ktoff + (uint32_t)(ntp * 32) + voff;
                ldmx4t(vh4, vh_s + off);
                ldmx4t(vl4, vl_s + off);
                mma16816(o[2 * ntp],     aph, vh4);
                mma16816(o[2 * ntp],     aph, vl4);
                mma16816(o[2 * ntp],     apl, vh4);
                mma16816(o[2 * ntp + 1], aph, vh4 + 2);
                mma16816(o[2 * ntp + 1], aph, vl4 + 2);
                mma16816(o[2 * ntp + 1], apl, vh4 + 2);
            }
        }
    }

    // ---- normalize + write pre-split bf16 [B,T,D]
    float il0 = 1.f / l0, il1 = 1.f / l1;
    size_t base0 = ((size_t)b * T_ + r0) * D_ + h * HD_;
    size_t base1 = ((size_t)b * T_ + r0 + 8) * D_ + h * HD_;
#pragma unroll
    for (int nt = 0; nt < 16; nt++) {
        uint32_t h0, lo0, h1, lo1;
        split2(o[nt][0] * il0, o[nt][1] * il0, h0, lo0);
        split2(o[nt][2] * il1, o[nt][3] * il1, h1, lo1);
        size_t c = nt * 8 + 2 * tig;
        *(uint32_t*)(OH + base0 + c) = h0;
        *(uint32_t*)(OL + base0 + c) = lo0;
        *(uint32_t*)(OH + base1 + c) = h1;
        *(uint32_t*)(OL + base1 + c) = lo1;
    }
}

// ---------------------------------------------------------------------------
extern "C" void kernel_launch(void* const* d_in, const int* in_sizes, int n_in,
                              void* d_out, int out_size)
{
    (void)in_sizes; (void)n_in; (void)out_size;
    const float* x    = (const float*)d_in[0];
    const float* wqkv = (const float*)d_in[2];
    const float* wout = (const float*)d_in[3];
    const float* bout = (const float*)d_in[4];
    float* outp = (float*)d_out;

    __nv_bfloat16 *qh_p, *ql_p, *kh_p, *kl_p, *vh_p, *vl_p;
    __nv_bfloat16 *xh_p, *xl_p, *w1h_p, *w1l_p, *w2h_p, *w2l_p, *ah_p, *al_p;
    cudaGetSymbolAddress((void**)&qh_p, g_qh);
    cudaGetSymbolAddress((void**)&ql_p, g_ql);
    cudaGetSymbolAddress((void**)&kh_p, g_kh);
    cudaGetSymbolAddress((void**)&kl_p, g_kl);
    cudaGetSymbolAddress((void**)&vh_p, g_vh);
    cudaGetSymbolAddress((void**)&vl_p, g_vl);
    cudaGetSymbolAddress((void**)&xh_p, g_xh);
    cudaGetSymbolAddress((void**)&xl_p, g_xl);
    cudaGetSymbolAddress((void**)&w1h_p, g_w1h);
    cudaGetSymbolAddress((void**)&w1l_p, g_w1l);
    cudaGetSymbolAddress((void**)&w2h_p, g_w2h);
    cudaGetSymbolAddress((void**)&w2l_p, g_w2l);
    cudaGetSymbolAddress((void**)&ah_p, g_ah);
    cudaGetSymbolAddress((void**)&al_p, g_al);

    cudaFuncSetAttribute(gemm_bf16<1>,
                         cudaFuncAttributeMaxDynamicSharedMemorySize, G2_SMEM_BYTES);
    cudaFuncSetAttribute(gemm_bf16<2>,
                         cudaFuncAttributeMaxDynamicSharedMemorySize, G2_SMEM_BYTES);
    cudaFuncSetAttribute(flash_hmma2,
                         cudaFuncAttributeMaxDynamicSharedMemorySize, FL_SMEM_BYTES);

    // 0) split inputs into bf16 hi/lo
    split_f32<<<592, 256>>>(x,    xh_p,  xl_p,  (B_ * T_ * D_) / 4);
    split_f32<<<592, 256>>>(wqkv, w1h_p, w1l_p, (3 * D_ * D_) / 4);
    split_f32<<<592, 256>>>(wout, w2h_p, w2l_p, (D_ * D_) / 4);

    // 1) QKV projection + fused split/scale epilogue
    dim3 g1((3 * D_) / 128, (B_ * T_) / 256);
    gemm_bf16<2><<<g1, 256, G2_SMEM_BYTES>>>(xh_p, xl_p, w1h_p, w1l_p,
                                             nullptr, nullptr,
                                             qh_p, ql_p, kh_p, kl_p, vh_p, vl_p,
                                             B_ * T_, 3 * D_, D_);

    // 2) causal flash attention -> pre-split bf16 output
    dim3 g2(T_ / 128, B_ * H_);
    flash_hmma2<<<g2, 256, FL_SMEM_BYTES>>>(qh_p, ql_p, kh_p, kl_p, vh_p, vl_p,
                                            ah_p, al_p);

    // 3) output projection + bias
    dim3 g3(D_ / 128, (B_ * T_) / 256);
    gemm_bf16<1><<<g3, 256, G2_SMEM_BYTES>>>(ah_p, al_p, w2h_p, w2l_p,
                                             bout, outp,
                                             nullptr, nullptr, nullptr, nullptr,
                                             nullptr, nullptr,
                                             B_ * T_, D_, D_);
}